// round 8
// baseline (speedup 1.0000x reference)
#include <cuda_runtime.h>
#include <cstdint>

#define BB   16
#define TENC 384
#define TDEC 200
#define HH   256
#define P2D  128
#define MELD 400
#define G3   768

#define NCTA 128
#define NTHR 256
#define TW   (NCTA * (NTHR / 32))
#define GT   (NCTA * NTHR)

// ---- persistent scratch (static __device__: allowed) ----
__device__ __align__(16) float sW1T[MELD * HH];
__device__ __align__(16) float sW2T[HH * P2D];
__device__ __align__(16) float sWihPreT[P2D * G3];
__device__ __align__(16) float sWaT[HH * G3];
__device__ __align__(16) float sWhhAT[HH * G3];
__device__ __align__(16) float sWqT[HH * HH];
__device__ __align__(16) float sProjT[2 * HH * HH];
__device__ __align__(16) float sDecWihT[2 * HH * G3];
__device__ __align__(16) float sDecWhhT[2 * HH * G3];
__device__ __align__(16) float sMelT[HH * MELD];
__device__ __align__(16) float sEncT[BB * HH * TENC];
__device__ __align__(16) float sPmT[BB * HH * TENC];
__device__ __align__(16) float sPn1[TDEC * BB * HH];
__device__ __align__(16) float sPn2[TDEC * BB * P2D];
__device__ __align__(16) float sGiPre[TDEC * BB * G3];
__device__ __align__(16) float sGiA[BB * G3];
__device__ __align__(16) float sGhA[BB * G3];
__device__ __align__(16) float sGiD[BB * G3];
__device__ __align__(16) float sGhD[BB * G3];
__device__ __align__(16) float sAttnH[BB * HH];
__device__ __align__(16) float sAtt[BB * HH];
__device__ __align__(16) float sPq[BB * HH];
__device__ __align__(16) float sE[BB * TENC];
__device__ __align__(16) float sAlign[BB * TENC];
__device__ __align__(16) float sDecIn[BB * HH];
__device__ __align__(16) float sDecIn2[BB * HH];
__device__ __align__(16) float sDecIn3[BB * HH];
__device__ __align__(16) float sD1[BB * HH];
__device__ __align__(16) float sD2[BB * HH];

__device__ unsigned long long gFlags[NCTA];
__device__ unsigned long long gEpochBase = 0ULL;

__device__ __forceinline__ void gbar(unsigned long long& epoch) {
    __threadfence();           // release my stores
    __syncthreads();
    epoch++;
    if (threadIdx.x < 32) {
        if (threadIdx.x == 0)
            *(volatile unsigned long long*)&gFlags[blockIdx.x] = epoch;
        const unsigned long long e = epoch;
        for (;;) {
            bool ok = true;
#pragma unroll
            for (int i = 0; i < NCTA / 32; i++)
                ok &= (*(volatile unsigned long long*)&gFlags[threadIdx.x + 32 * i] >= e);
            if (__all_sync(0xffffffffu, ok)) break;
        }
    }
    __syncthreads();
    __threadfence();           // CCTL.IVALL: drop stale L1 lines before reading peers' data
}

__device__ __forceinline__ float sigm(float x) {
    return __fdividef(1.f, 1.f + __expf(-x));
}
__device__ __forceinline__ float tanx(float x) {
    float e = __expf(-2.f * fabsf(x));
    return copysignf(__fdividef(1.f - e, 1.f + e), x);
}

template <int K, int J>
__device__ __forceinline__ float dotT(const float* __restrict__ WT, int j,
                                      const float* __restrict__ x) {
    float acc = 0.f;
#pragma unroll 4
    for (int k = 0; k < K; k += 4) {
        const float4 xv = *reinterpret_cast<const float4*>(x + k);
        acc = fmaf(xv.x, WT[(k + 0) * J + j], acc);
        acc = fmaf(xv.y, WT[(k + 1) * J + j], acc);
        acc = fmaf(xv.z, WT[(k + 2) * J + j], acc);
        acc = fmaf(xv.w, WT[(k + 3) * J + j], acc);
    }
    return acc;
}

__device__ __forceinline__ float gru_comb(const float* gi, const float* gh,
                                          int base, float h) {
    float r = sigm(gi[base] + gh[base]);
    float z = sigm(gi[base + HH] + gh[base + HH]);
    float n = tanx(gi[base + 2 * HH] + r * gh[base + 2 * HH]);
    return (1.f - z) * n + z * h;
}

__global__ void __launch_bounds__(NTHR, 1) decoder_persistent(
    const float* __restrict__ enc, const float* __restrict__ inputs,
    const int* __restrict__ memlen,
    const float* __restrict__ w1, const float* __restrict__ b1,
    const float* __restrict__ w2, const float* __restrict__ b2,
    const float* __restrict__ memw,
    const float* __restrict__ awih, const float* __restrict__ awhh,
    const float* __restrict__ abih, const float* __restrict__ abhh,
    const float* __restrict__ qw, const float* __restrict__ av,
    const float* __restrict__ projw, const float* __restrict__ projb,
    const float* __restrict__ dwih, const float* __restrict__ dwhh,
    const float* __restrict__ dbih, const float* __restrict__ dbhh,
    const float* __restrict__ melw, const float* __restrict__ melb,
    float* __restrict__ outMel, float* __restrict__ outAlign) {
    const int tid = threadIdx.x;
    const int lane = tid & 31;
    const int gt = blockIdx.x * NTHR + tid;
    const int gw = (tid >> 5) * NCTA + blockIdx.x;

    unsigned long long epoch = *(volatile unsigned long long*)&gEpochBase;

    // ---- P1: weight transposes, enc transpose, state zero ----
    for (int o = gt; o < BB * HH; o += GT) {
        sAttnH[o] = 0.f; sAtt[o] = 0.f; sD1[o] = 0.f; sD2[o] = 0.f;
    }
    for (int e = gt; e < MELD * HH; e += GT)
        sW1T[e] = w1[(e % HH) * MELD + e / HH];
    for (int e = gt; e < HH * P2D; e += GT)
        sW2T[e] = w2[(e % P2D) * HH + e / P2D];
    for (int e = gt; e < P2D * G3; e += GT)
        sWihPreT[e] = awih[(e % G3) * (HH + P2D) + e / G3];
    for (int e = gt; e < HH * G3; e += GT) {
        int k = e / G3, j = e % G3;
        sWaT[e] = awih[j * (HH + P2D) + P2D + k];
        sWhhAT[e] = awhh[j * HH + k];
    }
    for (int e = gt; e < HH * HH; e += GT)
        sWqT[e] = qw[(e % HH) * HH + e / HH];
    for (int e = gt; e < 2 * HH * HH; e += GT)
        sProjT[e] = projw[(e % HH) * (2 * HH) + e / HH];
    for (int e = gt; e < 2 * HH * G3; e += GT) {
        int c = e / (HH * G3), r = e % (HH * G3);
        int k = r / G3, j = r % G3;
        sDecWihT[e] = dwih[(c * G3 + j) * HH + k];
        sDecWhhT[e] = dwhh[(c * G3 + j) * HH + k];
    }
    for (int e = gt; e < HH * MELD; e += GT)
        sMelT[e] = melw[(e % MELD) * HH + e / MELD];
    for (int e = gt; e < BB * HH * TENC; e += GT) {
        int s = e % TENC, d = (e / TENC) % HH, b = e / (TENC * HH);
        sEncT[e] = enc[(b * TENC + s) * HH + d];
    }
    gbar(epoch);

    // ---- P2: processed_memory [b][i][s]  +  prenet layer 1 ----
    for (int c = gw; c * 32 < BB * HH * TENC; c += TW) {
        int o = c * 32 + lane;
        int s = o % TENC, bi = o / TENC, i = bi % HH, b = bi / HH;
        const float* wr = memw + i * HH;
        const float* eb = sEncT + b * HH * TENC + s;
        float acc = 0.f;
#pragma unroll 4
        for (int d = 0; d < HH; d += 4) {
            const float4 w4 = *reinterpret_cast<const float4*>(wr + d);
            acc = fmaf(w4.x, eb[(d + 0) * TENC], acc);
            acc = fmaf(w4.y, eb[(d + 1) * TENC], acc);
            acc = fmaf(w4.z, eb[(d + 2) * TENC], acc);
            acc = fmaf(w4.w, eb[(d + 3) * TENC], acc);
        }
        sPmT[o] = acc;
    }
    for (int c = gw; c * 32 < TDEC * BB * HH; c += TW) {
        int o = c * 32 + lane;
        int h = o % HH, tb = o / HH, t = tb / BB, b = tb % BB;
        float acc = b1[h];
        if (t > 0)
            acc += dotT<MELD, HH>(sW1T, h, inputs + (b * TDEC + t - 1) * MELD);
        sPn1[o] = fmaxf(acc, 0.f);
    }
    gbar(epoch);

    // ---- P3: prenet layer 2 ----
    for (int c = gw; c * 32 < TDEC * BB * P2D; c += TW) {
        int o = c * 32 + lane;
        int p = o % P2D, tb = o / P2D;
        sPn2[o] = fmaxf(b2[p] + dotT<HH, P2D>(sW2T, p, sPn1 + tb * HH), 0.f);
    }
    gbar(epoch);

    // ---- P4: gi_pre = bih + prenet-part of attention-GRU input gates ----
    for (int c = gw; c * 32 < TDEC * BB * G3; c += TW) {
        int o = c * 32 + lane;
        int j = o % G3, tb = o / G3;
        sGiPre[o] = abih[j] + dotT<P2D, G3>(sWihPreT, j, sPn2 + tb * P2D);
    }
    gbar(epoch);

    // ---- sequential decode ----
    for (int t = 0; t < TDEC; t++) {
        // S1: attn-GRU gate GEMVs
        for (int c = gw; c * 32 < 2 * BB * G3; c += TW) {
            int o = c * 32 + lane;
            int r = o % (BB * G3), j = r % G3, b = r / G3;
            if (o < BB * G3)
                sGiA[r] = sGiPre[(t * BB + b) * G3 + j] +
                          dotT<HH, G3>(sWaT, j, sAtt + b * HH);
            else
                sGhA[r] = abhh[j] + dotT<HH, G3>(sWhhAT, j, sAttnH + b * HH);
        }
        gbar(epoch);
        // S2: attn-GRU combine
        for (int c = gw; c * 32 < BB * HH; c += TW) {
            int o = c * 32 + lane;
            sAttnH[o] = gru_comb(sGiA, sGhA, (o / HH) * G3 + (o % HH), sAttnH[o]);
        }
        gbar(epoch);
        // S3: pq = attn_h @ Wq^T
        for (int c = gw; c * 32 < BB * HH; c += TW) {
            int o = c * 32 + lane;
            sPq[o] = dotT<HH, HH>(sWqT, o % HH, sAttnH + (o / HH) * HH);
        }
        gbar(epoch);
        // S4: energies
        for (int c = gw; c * 32 < BB * TENC; c += TW) {
            int o = c * 32 + lane;
            int s = o % TENC, b = o / TENC;
            const float* pq = sPq + b * HH;
            const float* pmb = sPmT + b * HH * TENC + s;
            float acc = 0.f;
#pragma unroll 2
            for (int i = 0; i < HH; i += 4) {
                const float4 q4 = *reinterpret_cast<const float4*>(pq + i);
                const float4 v4 = *reinterpret_cast<const float4*>(av + i);
                acc = fmaf(v4.x, tanx(q4.x + pmb[(i + 0) * TENC]), acc);
                acc = fmaf(v4.y, tanx(q4.y + pmb[(i + 1) * TENC]), acc);
                acc = fmaf(v4.z, tanx(q4.z + pmb[(i + 2) * TENC]), acc);
                acc = fmaf(v4.w, tanx(q4.w + pmb[(i + 3) * TENC]), acc);
            }
            sE[o] = (s < memlen[b]) ? acc : -1e30f;
        }
        gbar(epoch);
        // S5: softmax (one warp per batch row) + alignment output
        for (int b = gw; b < BB; b += TW) {
            float v[TENC / 32];
#pragma unroll
            for (int k = 0; k < TENC / 32; k++) v[k] = sE[b * TENC + lane + 32 * k];
            float m = v[0];
#pragma unroll
            for (int k = 1; k < TENC / 32; k++) m = fmaxf(m, v[k]);
#pragma unroll
            for (int off = 16; off > 0; off >>= 1)
                m = fmaxf(m, __shfl_xor_sync(0xffffffffu, m, off));
            float ex[TENC / 32], sum = 0.f;
#pragma unroll
            for (int k = 0; k < TENC / 32; k++) { ex[k] = __expf(v[k] - m); sum += ex[k]; }
#pragma unroll
            for (int off = 16; off > 0; off >>= 1)
                sum += __shfl_xor_sync(0xffffffffu, sum, off);
            float inv = __fdividef(1.f, sum);
#pragma unroll
            for (int k = 0; k < TENC / 32; k++) {
                float a = ex[k] * inv;
                int s = lane + 32 * k;
                sAlign[b * TENC + s] = a;
                outAlign[(b * TDEC + t) * TENC + s] = a;
            }
        }
        gbar(epoch);
        // S6: context = align @ enc
        for (int c = gw; c * 32 < BB * HH; c += TW) {
            int o = c * 32 + lane;
            int d = o % HH, b = o / HH;
            const float* al = sAlign + b * TENC;
            const float* eb = enc + (b * TENC) * HH + d;
            float acc = 0.f;
#pragma unroll 4
            for (int s = 0; s < TENC; s += 4) {
                const float4 a4 = *reinterpret_cast<const float4*>(al + s);
                acc = fmaf(a4.x, eb[(s + 0) * HH], acc);
                acc = fmaf(a4.y, eb[(s + 1) * HH], acc);
                acc = fmaf(a4.z, eb[(s + 2) * HH], acc);
                acc = fmaf(a4.w, eb[(s + 3) * HH], acc);
            }
            sAtt[o] = acc;
        }
        gbar(epoch);
        // S7: dec_in = [attn_h, att] @ proj^T + b
        for (int c = gw; c * 32 < BB * HH; c += TW) {
            int o = c * 32 + lane;
            int i = o % HH, b = o / HH;
            sDecIn[o] = projb[i] + dotT<HH, HH>(sProjT, i, sAttnH + b * HH) +
                        dotT<HH, HH>(sProjT + HH * HH, i, sAtt + b * HH);
        }
        gbar(epoch);
        // S8: decoder GRU 0 gates
        for (int c = gw; c * 32 < 2 * BB * G3; c += TW) {
            int o = c * 32 + lane;
            int r = o % (BB * G3), j = r % G3, b = r / G3;
            if (o < BB * G3)
                sGiD[r] = dbih[j] + dotT<HH, G3>(sDecWihT, j, sDecIn + b * HH);
            else
                sGhD[r] = dbhh[j] + dotT<HH, G3>(sDecWhhT, j, sD1 + b * HH);
        }
        gbar(epoch);
        // S9: combine 0 + residual
        for (int c = gw; c * 32 < BB * HH; c += TW) {
            int o = c * 32 + lane;
            float nh = gru_comb(sGiD, sGhD, (o / HH) * G3 + (o % HH), sD1[o]);
            sD1[o] = nh;
            sDecIn2[o] = nh + sDecIn[o];
        }
        gbar(epoch);
        // S10: decoder GRU 1 gates
        for (int c = gw; c * 32 < 2 * BB * G3; c += TW) {
            int o = c * 32 + lane;
            int r = o % (BB * G3), j = r % G3, b = r / G3;
            if (o < BB * G3)
                sGiD[r] = dbih[G3 + j] +
                          dotT<HH, G3>(sDecWihT + HH * G3, j, sDecIn2 + b * HH);
            else
                sGhD[r] = dbhh[G3 + j] +
                          dotT<HH, G3>(sDecWhhT + HH * G3, j, sD2 + b * HH);
        }
        gbar(epoch);
        // S11: combine 1 + residual
        for (int c = gw; c * 32 < BB * HH; c += TW) {
            int o = c * 32 + lane;
            float nh = gru_comb(sGiD, sGhD, (o / HH) * G3 + (o % HH), sD2[o]);
            sD2[o] = nh;
            sDecIn3[o] = nh + sDecIn2[o];
        }
        gbar(epoch);
        // S12: mel projection -> output (no trailing barrier needed: next
        // phase (S1 of t+1) writes only sGiA/sGhA, which S12 never reads)
        for (int c = gw; c * 32 < BB * MELD; c += TW) {
            int o = c * 32 + lane;
            int m = o % MELD, b = o / MELD;
            outMel[(b * TDEC + t) * MELD + m] =
                melb[m] + dotT<HH, MELD>(sMelT, m, sDecIn3 + b * HH);
        }
    }

    gbar(epoch);   // all CTAs done (also orders final S12 stores)
    if (blockIdx.x == 0 && tid == 0)
        *(volatile unsigned long long*)&gEpochBase = epoch;
}

extern "C" void kernel_launch(void* const* d_in, const int* in_sizes, int n_in,
                              void* d_out, int out_size) {
    (void)in_sizes; (void)n_in;
    float* outMel = (float*)d_out;
    float* outAlign = outMel + (size_t)BB * TDEC * MELD;
    decoder_persistent<<<NCTA, NTHR>>>(
        (const float*)d_in[0], (const float*)d_in[1], (const int*)d_in[2],
        (const float*)d_in[3], (const float*)d_in[4],
        (const float*)d_in[5], (const float*)d_in[6],
        (const float*)d_in[7],
        (const float*)d_in[8], (const float*)d_in[9],
        (const float*)d_in[10], (const float*)d_in[11],
        (const float*)d_in[12], (const float*)d_in[13],
        (const float*)d_in[14], (const float*)d_in[15],
        (const float*)d_in[16], (const float*)d_in[17],
        (const float*)d_in[18], (const float*)d_in[19],
        (const float*)d_in[20], (const float*)d_in[21],
        outMel, outAlign);
}

// round 14
// speedup vs baseline: 1.2697x; 1.2697x over previous
#include <cuda_runtime.h>
#include <cstdint>

#define BB   16
#define TENC 384
#define TDEC 200
#define HH   256
#define P2D  128
#define MELD 400
#define G3   768

#define NCTA 128
#define NTHR 256
#define GT   (NCTA * NTHR)

// ---------------- global scratch (zero-initialized by CUDA) ----------------
__device__ __align__(16) float sW1T[MELD * HH];
__device__ __align__(16) float sW2T[HH * P2D];
__device__ __align__(16) float sWihPreT[P2D * G3];
__device__ __align__(16) float sWmT[HH * HH];
__device__ __align__(16) float sPm[BB * TENC * HH];    // [b][s][i]
__device__ __align__(16) float sEncT[BB * HH * TENC];  // [b][d][s]
__device__ __align__(16) float sPn1[TDEC * BB * HH];
__device__ __align__(16) float sPn2[TDEC * BB * P2D];
__device__ __align__(16) float sGiPre[TDEC * BB * G3];
// per-step state / intermediates (global coherence via threadfence barrier)
__device__ __align__(16) float gGiA[BB * G3];
__device__ __align__(16) float gGhA[BB * G3];
__device__ __align__(16) float gGiD0[BB * G3];
__device__ __align__(16) float gGhD0[BB * G3];
__device__ __align__(16) float gGiD1[BB * G3];
__device__ __align__(16) float gGhD1[BB * G3];
__device__ __align__(16) float gAttnH[BB * HH];
__device__ __align__(16) float gD1[BB * HH];
__device__ __align__(16) float gD2[BB * HH];
__device__ __align__(16) float gAtt[BB * HH];
__device__ __align__(16) float gPq[BB * HH];
__device__ __align__(16) float gE[BB * TENC];
__device__ __align__(16) float gDecIn[BB * HH];
__device__ __align__(16) float gDecIn2[BB * HH];
__device__ __align__(16) float gDecIn3[BB * HH];

__device__ unsigned long long gFlags[NCTA];
__device__ unsigned long long gEpochBase = 0ULL;

// ---- PROVEN barrier (identical to the R8 kernel that passed @5.7e-7) ----
__device__ __forceinline__ void gbar(unsigned long long& epoch) {
    __threadfence();           // release my stores (MEMBAR.GPU)
    __syncthreads();
    epoch++;
    if (threadIdx.x < 32) {
        if (threadIdx.x == 0)
            *(volatile unsigned long long*)&gFlags[blockIdx.x] = epoch;
        for (;;) {
            bool ok = true;
#pragma unroll
            for (int i = 0; i < NCTA / 32; i++)
                ok &= (*(volatile unsigned long long*)&gFlags[threadIdx.x + 32 * i] >= epoch);
            if (__all_sync(0xffffffffu, ok)) break;
        }
    }
    __syncthreads();
    __threadfence();           // CCTL.IVALL: drop stale L1 lines before reads
}

__device__ __forceinline__ float sigm(float x) {
    return __fdividef(1.f, 1.f + __expf(-x));
}
__device__ __forceinline__ float tanx(float x) {
    float e = __expf(-2.f * fabsf(x));
    return copysignf(__fdividef(1.f - e, 1.f + e), x);
}

// global-weight dot (precompute phases): WT[k*J + j]
template <int K, int J>
__device__ __forceinline__ float dotT(const float* __restrict__ WT, int j,
                                      const float* __restrict__ x) {
    float acc = 0.f;
#pragma unroll 4
    for (int k = 0; k < K; k += 4) {
        const float4 xv = *reinterpret_cast<const float4*>(x + k);
        acc = fmaf(xv.x, WT[(k + 0) * J + j], acc);
        acc = fmaf(xv.y, WT[(k + 1) * J + j], acc);
        acc = fmaf(xv.z, WT[(k + 2) * J + j], acc);
        acc = fmaf(xv.w, WT[(k + 3) * J + j], acc);
    }
    return acc;
}

// smem-weight dot: w[k*W + jl], x in global (L1-cached), K elements
template <int K, int W>
__device__ __forceinline__ float dotS(const float* w, int jl,
                                      const float* __restrict__ x) {
    float acc = 0.f;
#pragma unroll 8
    for (int k = 0; k < K; k += 4) {
        const float4 xv = *reinterpret_cast<const float4*>(x + k);
        acc = fmaf(xv.x, w[(k + 0) * W + jl], acc);
        acc = fmaf(xv.y, w[(k + 1) * W + jl], acc);
        acc = fmaf(xv.z, w[(k + 2) * W + jl], acc);
        acc = fmaf(xv.w, w[(k + 3) * W + jl], acc);
    }
    return acc;
}

// dynamic smem layout (floats)
#define SM_WG1 0          // 12*256  gate slice: attn (Wa | Whh)
#define SM_WG2 3072       // 12*256  gate slice: dec0
#define SM_WG3 6144       // 12*256  gate slice: dec1
#define SM_WQ  9216       // 2*256
#define SM_WP  9728       // 2*512
#define SM_WM  10752      // 4*256
#define SM_AL  11776      // 16*384 softmax/align buffer
#define SM_FLOATS 17920   // 71680 bytes

__global__ void __launch_bounds__(NTHR, 1) decoder_persistent(
    const float* __restrict__ enc, const float* __restrict__ inputs,
    const int* __restrict__ memlen,
    const float* __restrict__ w1, const float* __restrict__ b1,
    const float* __restrict__ w2, const float* __restrict__ b2,
    const float* __restrict__ memw,
    const float* __restrict__ awih, const float* __restrict__ awhh,
    const float* __restrict__ abih, const float* __restrict__ abhh,
    const float* __restrict__ qw, const float* __restrict__ av,
    const float* __restrict__ projw, const float* __restrict__ projb,
    const float* __restrict__ dwih, const float* __restrict__ dwhh,
    const float* __restrict__ dbih, const float* __restrict__ dbhh,
    const float* __restrict__ melw, const float* __restrict__ melb,
    float* __restrict__ outMel, float* __restrict__ outAlign) {
    extern __shared__ float sm[];
    const int tid = threadIdx.x;
    const int lane = tid & 31;
    const int c = blockIdx.x;
    const int gt = c * NTHR + tid;

    unsigned long long epoch = *(volatile unsigned long long*)&gEpochBase;

    // ======== P1: smem weight slices + global transposes + state zero ========
    for (int e = tid; e < 12 * 256; e += NTHR) {
        int k = e / 12, jl = e % 12;
        if (c < 64) {
            int j = c * 12 + jl;
            sm[SM_WG1 + e] = awih[j * (HH + P2D) + P2D + k];
            sm[SM_WG2 + e] = dwih[j * HH + k];
            sm[SM_WG3 + e] = dwih[(G3 + j) * HH + k];
        } else {
            int j = (c - 64) * 12 + jl;
            sm[SM_WG1 + e] = awhh[j * HH + k];
            sm[SM_WG2 + e] = dwhh[j * HH + k];
            sm[SM_WG3 + e] = dwhh[(G3 + j) * HH + k];
        }
    }
    for (int e = tid; e < 512; e += NTHR) {
        int k = e / 2, il = e % 2;
        sm[SM_WQ + e] = qw[(c * 2 + il) * HH + k];
    }
    for (int e = tid; e < 1024; e += NTHR) {
        int k = e / 2, il = e % 2;
        sm[SM_WP + e] = projw[(c * 2 + il) * (2 * HH) + k];
    }
    if (c < 100)
        for (int e = tid; e < 1024; e += NTHR) {
            int k = e / 4, ml = e % 4;
            sm[SM_WM + e] = melw[(c * 4 + ml) * HH + k];
        }

    for (int o = gt; o < BB * HH; o += GT) {
        gAttnH[o] = 0.f; gD1[o] = 0.f; gD2[o] = 0.f; gAtt[o] = 0.f;
    }
    for (int e = gt; e < MELD * HH; e += GT)
        sW1T[e] = w1[(e % HH) * MELD + e / HH];
    for (int e = gt; e < HH * P2D; e += GT)
        sW2T[e] = w2[(e % P2D) * HH + e / P2D];
    for (int e = gt; e < P2D * G3; e += GT)
        sWihPreT[e] = awih[(e % G3) * (HH + P2D) + e / G3];
    for (int e = gt; e < HH * HH; e += GT)
        sWmT[e] = memw[(e % HH) * HH + e / HH];
    for (int e = gt; e < BB * HH * TENC; e += GT) {
        int s = e % TENC, d = (e / TENC) % HH, b = e / (TENC * HH);
        sEncT[e] = enc[(b * TENC + s) * HH + d];
    }
    gbar(epoch);

    // ======== P2: processed_memory [b][s][i] + prenet layer1 ========
    for (int o = gt; o < BB * TENC * HH; o += GT) {
        int i = o % HH, sb = o / HH;
        sPm[o] = dotT<HH, HH>(sWmT, i, enc + sb * HH);
    }
    for (int o = gt; o < TDEC * BB * HH; o += GT) {
        int h = o % HH, tb = o / HH, t = tb / BB, b = tb % BB;
        float acc = b1[h];
        if (t > 0)
            acc += dotT<MELD, HH>(sW1T, h, inputs + (b * TDEC + t - 1) * MELD);
        sPn1[o] = fmaxf(acc, 0.f);
    }
    gbar(epoch);

    // ======== P3: prenet layer2 ========
    for (int o = gt; o < TDEC * BB * P2D; o += GT) {
        int p = o % P2D, tb = o / P2D;
        sPn2[o] = fmaxf(b2[p] + dotT<HH, P2D>(sW2T, p, sPn1 + tb * HH), 0.f);
    }
    gbar(epoch);

    // ======== P4: gi_pre = abih + prenet part of attn-GRU gates ========
    for (int o = gt; o < TDEC * BB * G3; o += GT) {
        int j = o % G3, tb = o / G3;
        sGiPre[o] = abih[j] + dotT<P2D, G3>(sWihPreT, j, sPn2 + tb * P2D);
    }
    gbar(epoch);

    // ================= sequential decode =================
    for (int tt = 0; tt < TDEC; tt++) {
        // -- Ph1: attention-GRU gate GEMVs (c<64: gi slice, c>=64: gh slice) --
        if (tid < 192) {
            int b = tid / 12, jl = tid % 12;
            if (c < 64) {
                int j = c * 12 + jl;
                float acc = dotS<HH, 12>(sm + SM_WG1, jl, gAtt + b * HH);
                gGiA[b * G3 + j] = sGiPre[(tt * BB + b) * G3 + j] + acc;
            } else {
                int j = (c - 64) * 12 + jl;
                float acc = dotS<HH, 12>(sm + SM_WG1, jl, gAttnH + b * HH);
                gGhA[b * G3 + j] = abhh[j] + acc;
            }
        }
        gbar(epoch);

        // -- Ph2: attn-GRU combine (32 elems per CTA, in-place) --
        if (tid < 32) {
            int o = c * 32 + tid, b = o >> 8, j = o & 255;
            const float* gi = gGiA + b * G3;
            const float* gh = gGhA + b * G3;
            float r = sigm(gi[j] + gh[j]);
            float z = sigm(gi[HH + j] + gh[HH + j]);
            float n = tanx(gi[2 * HH + j] + r * gh[2 * HH + j]);
            gAttnH[o] = (1.f - z) * n + z * gAttnH[o];
        }
        gbar(epoch);

        // -- Ph3: pq (2 cols x 16 b per CTA, split-K 4) --
        if (tid < 128) {
            int dd = tid >> 2, kq = tid & 3;
            int il = dd >> 4, b = dd & 15;
            float acc = 0.f;
            const float* x = gAttnH + b * HH + kq * 64;
            const float* w = sm + SM_WQ + kq * 64 * 2;
#pragma unroll 8
            for (int k = 0; k < 64; k += 4) {
                const float4 xv = *reinterpret_cast<const float4*>(x + k);
                acc = fmaf(xv.x, w[(k + 0) * 2 + il], acc);
                acc = fmaf(xv.y, w[(k + 1) * 2 + il], acc);
                acc = fmaf(xv.z, w[(k + 2) * 2 + il], acc);
                acc = fmaf(xv.w, w[(k + 3) * 2 + il], acc);
            }
            acc += __shfl_xor_sync(0xffffffffu, acc, 1);
            acc += __shfl_xor_sync(0xffffffffu, acc, 2);
            if (kq == 0) gPq[b * HH + c * 2 + il] = acc;
        }
        gbar(epoch);

        // -- Ph4: energies (warp per (b,s), 6 per warp) --
        {
            const int gwarp = (c << 3) + (tid >> 5);
#pragma unroll
            for (int k = 0; k < 6; k++) {
                int o = gwarp + (k << 10);              // < 6144
                int b = o / TENC, s = o - b * TENC;
                const float4* pq = reinterpret_cast<const float4*>(gPq + b * HH);
                float4 q0 = pq[lane], q1 = pq[32 + lane];
                const float4* pm =
                    reinterpret_cast<const float4*>(sPm + (b * TENC + s) * HH);
                float4 m0 = pm[lane], m1 = pm[32 + lane];
                const float4* vv = reinterpret_cast<const float4*>(av);
                float4 v0 = vv[lane], v1 = vv[32 + lane];
                float acc = v0.x * tanx(q0.x + m0.x);
                acc = fmaf(v0.y, tanx(q0.y + m0.y), acc);
                acc = fmaf(v0.z, tanx(q0.z + m0.z), acc);
                acc = fmaf(v0.w, tanx(q0.w + m0.w), acc);
                acc = fmaf(v1.x, tanx(q1.x + m1.x), acc);
                acc = fmaf(v1.y, tanx(q1.y + m1.y), acc);
                acc = fmaf(v1.z, tanx(q1.z + m1.z), acc);
                acc = fmaf(v1.w, tanx(q1.w + m1.w), acc);
#pragma unroll
                for (int off = 16; off > 0; off >>= 1)
                    acc += __shfl_xor_sync(0xffffffffu, acc, off);
                if (lane == 0)
                    gE[o] = (s < memlen[b]) ? acc : -1e30f;
            }
        }
        gbar(epoch);

        // -- Ph5: softmax (all 16 b per CTA, into smem) + context slice --
        {
            float* smAl = sm + SM_AL;
            const int w = tid >> 5;
#pragma unroll
            for (int bi = 0; bi < 2; bi++) {
                int b = 2 * w + bi;
                float v[TENC / 32];
#pragma unroll
                for (int k = 0; k < TENC / 32; k++)
                    v[k] = gE[b * TENC + lane + 32 * k];
                float m = v[0];
#pragma unroll
                for (int k = 1; k < TENC / 32; k++) m = fmaxf(m, v[k]);
#pragma unroll
                for (int off = 16; off > 0; off >>= 1)
                    m = fmaxf(m, __shfl_xor_sync(0xffffffffu, m, off));
                float sum = 0.f;
#pragma unroll
                for (int k = 0; k < TENC / 32; k++) {
                    v[k] = __expf(v[k] - m);
                    sum += v[k];
                }
#pragma unroll
                for (int off = 16; off > 0; off >>= 1)
                    sum += __shfl_xor_sync(0xffffffffu, sum, off);
                float inv = __fdividef(1.f, sum);
#pragma unroll
                for (int k = 0; k < TENC / 32; k++) {
                    float a = v[k] * inv;
                    int s = lane + 32 * k;
                    smAl[b * TENC + s] = a;
                    if (c == 0)
                        outAlign[(b * TDEC + tt) * TENC + s] = a;
                }
            }
            __syncthreads();
            if (tid < 128) {
                int dl = tid >> 6, b = (tid >> 2) & 15, q = tid & 3;
                int d = c * 2 + dl;
                const float* al = smAl + b * TENC + q * 96;
                const float* eb = sEncT + (b * HH + d) * TENC + q * 96;
                float acc = 0.f;
#pragma unroll 6
                for (int s = 0; s < 96; s += 4) {
                    const float4 a4 = *reinterpret_cast<const float4*>(al + s);
                    const float4 e4 = *reinterpret_cast<const float4*>(eb + s);
                    acc = fmaf(a4.x, e4.x, acc);
                    acc = fmaf(a4.y, e4.y, acc);
                    acc = fmaf(a4.z, e4.z, acc);
                    acc = fmaf(a4.w, e4.w, acc);
                }
                acc += __shfl_xor_sync(0xffffffffu, acc, 1);
                acc += __shfl_xor_sync(0xffffffffu, acc, 2);
                if (q == 0) gAtt[b * HH + d] = acc;
            }
        }
        gbar(epoch);

        // -- Ph6: dec_in projection (2 cols x 16 b, split-K 8 over 512) --
        {
            int dd = tid >> 3, kq = tid & 7;
            int il = dd >> 4, b = dd & 15;
            const float* x = (kq < 4) ? (gAttnH + b * HH + kq * 64)
                                      : (gAtt + b * HH + (kq - 4) * 64);
            const float* w = sm + SM_WP + kq * 64 * 2;
            float acc = 0.f;
#pragma unroll 8
            for (int k = 0; k < 64; k += 4) {
                const float4 xv = *reinterpret_cast<const float4*>(x + k);
                acc = fmaf(xv.x, w[(k + 0) * 2 + il], acc);
                acc = fmaf(xv.y, w[(k + 1) * 2 + il], acc);
                acc = fmaf(xv.z, w[(k + 2) * 2 + il], acc);
                acc = fmaf(xv.w, w[(k + 3) * 2 + il], acc);
            }
            acc += __shfl_xor_sync(0xffffffffu, acc, 1);
            acc += __shfl_xor_sync(0xffffffffu, acc, 2);
            acc += __shfl_xor_sync(0xffffffffu, acc, 4);
            if (kq == 0) {
                int i = c * 2 + il;
                gDecIn[b * HH + i] = projb[i] + acc;
            }
        }
        gbar(epoch);

        // -- Ph7: decoder GRU0 gates --
        if (tid < 192) {
            int b = tid / 12, jl = tid % 12;
            if (c < 64) {
                int j = c * 12 + jl;
                float acc = dotS<HH, 12>(sm + SM_WG2, jl, gDecIn + b * HH);
                gGiD0[b * G3 + j] = dbih[j] + acc;
            } else {
                int j = (c - 64) * 12 + jl;
                float acc = dotS<HH, 12>(sm + SM_WG2, jl, gD1 + b * HH);
                gGhD0[b * G3 + j] = dbhh[j] + acc;
            }
        }
        gbar(epoch);

        // -- Ph8: combine0 + residual --
        if (tid < 32) {
            int o = c * 32 + tid, b = o >> 8, j = o & 255;
            const float* gi = gGiD0 + b * G3;
            const float* gh = gGhD0 + b * G3;
            float r = sigm(gi[j] + gh[j]);
            float z = sigm(gi[HH + j] + gh[HH + j]);
            float n = tanx(gi[2 * HH + j] + r * gh[2 * HH + j]);
            float hnew = (1.f - z) * n + z * gD1[o];
            gD1[o] = hnew;
            gDecIn2[o] = hnew + gDecIn[o];
        }
        gbar(epoch);

        // -- Ph9: decoder GRU1 gates --
        if (tid < 192) {
            int b = tid / 12, jl = tid % 12;
            if (c < 64) {
                int j = c * 12 + jl;
                float acc = dotS<HH, 12>(sm + SM_WG3, jl, gDecIn2 + b * HH);
                gGiD1[b * G3 + j] = dbih[G3 + j] + acc;
            } else {
                int j = (c - 64) * 12 + jl;
                float acc = dotS<HH, 12>(sm + SM_WG3, jl, gD2 + b * HH);
                gGhD1[b * G3 + j] = dbhh[G3 + j] + acc;
            }
        }
        gbar(epoch);

        // -- Ph10: combine1 + residual --
        if (tid < 32) {
            int o = c * 32 + tid, b = o >> 8, j = o & 255;
            const float* gi = gGiD1 + b * G3;
            const float* gh = gGhD1 + b * G3;
            float r = sigm(gi[j] + gh[j]);
            float z = sigm(gi[HH + j] + gh[HH + j]);
            float n = tanx(gi[2 * HH + j] + r * gh[2 * HH + j]);
            float hnew = (1.f - z) * n + z * gD2[o];
            gD2[o] = hnew;
            gDecIn3[o] = hnew + gDecIn2[o];
        }
        gbar(epoch);

        // -- Ph11: mel projection (CTAs 0..99: 4 cols x 16 b, split-K 4) --
        // no trailing barrier: next step's Ph1 writes only gGiA/gGhA (not read
        // here) and its end-barrier orders everything else.
        if (c < 100) {
            int dd = tid >> 2, kq = tid & 3;
            int ml = dd >> 4, b = dd & 15;
            const float* x = gDecIn3 + b * HH + kq * 64;
            const float* w = sm + SM_WM + kq * 64 * 4;
            float acc = 0.f;
#pragma unroll 8
            for (int k = 0; k < 64; k += 4) {
                const float4 xv = *reinterpret_cast<const float4*>(x + k);
                acc = fmaf(xv.x, w[(k + 0) * 4 + ml], acc);
                acc = fmaf(xv.y, w[(k + 1) * 4 + ml], acc);
                acc = fmaf(xv.z, w[(k + 2) * 4 + ml], acc);
                acc = fmaf(xv.w, w[(k + 3) * 4 + ml], acc);
            }
            acc += __shfl_xor_sync(0xffffffffu, acc, 1);
            acc += __shfl_xor_sync(0xffffffffu, acc, 2);
            if (kq == 0) {
                int m = c * 4 + ml;
                outMel[(b * TDEC + tt) * MELD + m] = melb[m] + acc;
            }
        }
    }

    gbar(epoch);   // orders final Ph11 stores; all CTAs done
    if (c == 0 && tid == 0)
        *(volatile unsigned long long*)&gEpochBase = epoch;
}

extern "C" void kernel_launch(void* const* d_in, const int* in_sizes, int n_in,
                              void* d_out, int out_size) {
    (void)in_sizes; (void)n_in; (void)out_size;
    float* outMel = (float*)d_out;
    float* outAlign = outMel + (size_t)BB * TDEC * MELD;
    cudaFuncSetAttribute(decoder_persistent,
                         cudaFuncAttributeMaxDynamicSharedMemorySize,
                         SM_FLOATS * sizeof(float));
    decoder_persistent<<<NCTA, NTHR, SM_FLOATS * sizeof(float)>>>(
        (const float*)d_in[0], (const float*)d_in[1], (const int*)d_in[2],
        (const float*)d_in[3], (const float*)d_in[4],
        (const float*)d_in[5], (const float*)d_in[6],
        (const float*)d_in[7],
        (const float*)d_in[8], (const float*)d_in[9],
        (const float*)d_in[10], (const float*)d_in[11],
        (const float*)d_in[12], (const float*)d_in[13],
        (const float*)d_in[14], (const float*)d_in[15],
        (const float*)d_in[16], (const float*)d_in[17],
        (const float*)d_in[18], (const float*)d_in[19],
        (const float*)d_in[20], (const float*)d_in[21],
        outMel, outAlign);
}

// round 15
// speedup vs baseline: 2.0508x; 1.6152x over previous
#include <cuda_runtime.h>
#include <cstdint>

#define BB   16
#define TENC 384
#define TDEC 200
#define HH   256
#define P2D  128
#define MELD 400
#define G3   768

#define NCTA 128
#define NTHR 256
#define GT   (NCTA * NTHR)

// ---------------- global scratch (zero-initialized by CUDA) ----------------
__device__ __align__(16) float sW1T[MELD * HH];
__device__ __align__(16) float sW2T[HH * P2D];
__device__ __align__(16) float sWihPreT[P2D * G3];
__device__ __align__(16) float sWmT[HH * HH];
__device__ __align__(16) float sPm[BB * TENC * HH];    // [b][s][i]
__device__ __align__(16) float sEncT[BB * HH * TENC];  // [b][d][s]
__device__ __align__(16) float sPn1[TDEC * BB * HH];
__device__ __align__(16) float sPn2[TDEC * BB * P2D];
__device__ __align__(16) float sGiPre[TDEC * BB * G3];
// per-step state / intermediates
__device__ __align__(16) float gGiA[BB * G3];
__device__ __align__(16) float gGhA[BB * G3];
__device__ __align__(16) float gGiD0[BB * G3];
__device__ __align__(16) float gGhD0[BB * G3];
__device__ __align__(16) float gGiD1[BB * G3];
__device__ __align__(16) float gGhD1[BB * G3];
__device__ __align__(16) float gAttnH[BB * HH];
__device__ __align__(16) float gD1[BB * HH];
__device__ __align__(16) float gD2[BB * HH];
__device__ __align__(16) float gAtt[BB * HH];
__device__ __align__(16) float gPq[BB * HH];
__device__ __align__(16) float gE[BB * TENC];
__device__ __align__(16) float gDecIn[BB * HH];
__device__ __align__(16) float gDecIn2[BB * HH];
__device__ __align__(16) float gDecIn3[BB * HH];

// flags padded to 128B: one LTS line per CTA (parallel RED streams)
__device__ unsigned long long gFlags[NCTA * 16];
__device__ unsigned long long gEpochBase = 0ULL;

// ---- low-fence grid barrier ----
// Writer side: per-thread red.release (orders that thread's prior stores to
// gpu scope; NO MEMBAR, NO per-warp IVALL).
// Reader side: warp0 acquire-polls all 128 flags, then ONE __threadfence()
// (single CCTL.IVALL flushes this SM's L1 so every subsequent plain load
// misses to coherent L2), then __syncthreads releases the CTA.
__device__ __forceinline__ void gbar(unsigned long long& epoch) {
    epoch++;
    asm volatile("red.release.gpu.global.add.u64 [%0], 1;"
                 :: "l"(&gFlags[blockIdx.x * 16]) : "memory");
    if (threadIdx.x < 32) {
        const unsigned long long tgt = (unsigned long long)NTHR * epoch;
        int spins = 0;
        for (;;) {
            bool ok = true;
#pragma unroll
            for (int i = 0; i < NCTA / 32; i++) {
                unsigned long long v;
                asm volatile("ld.acquire.gpu.global.u64 %0, [%1];"
                             : "=l"(v)
                             : "l"(&gFlags[(threadIdx.x + 32 * i) * 16])
                             : "memory");
                ok &= (v >= tgt);
            }
            if (__all_sync(0xffffffffu, ok)) break;
            if (++spins > 4) __nanosleep(40);
        }
        __threadfence();   // one IVALL per CTA: drop stale L1 lines
    }
    __syncthreads();
}

__device__ __forceinline__ float sigm(float x) {
    return __fdividef(1.f, 1.f + __expf(-x));
}
__device__ __forceinline__ float tanx(float x) {
    float e = __expf(-2.f * fabsf(x));
    return copysignf(__fdividef(1.f - e, 1.f + e), x);
}

// global-weight dot (precompute phases): WT[k*J + j]
template <int K, int J>
__device__ __forceinline__ float dotT(const float* __restrict__ WT, int j,
                                      const float* __restrict__ x) {
    float acc = 0.f;
#pragma unroll 4
    for (int k = 0; k < K; k += 4) {
        const float4 xv = *reinterpret_cast<const float4*>(x + k);
        acc = fmaf(xv.x, WT[(k + 0) * J + j], acc);
        acc = fmaf(xv.y, WT[(k + 1) * J + j], acc);
        acc = fmaf(xv.z, WT[(k + 2) * J + j], acc);
        acc = fmaf(xv.w, WT[(k + 3) * J + j], acc);
    }
    return acc;
}

// smem-weight dot: w[k*W + jl], x in global, K elements
template <int K, int W>
__device__ __forceinline__ float dotS(const float* w, int jl,
                                      const float* __restrict__ x) {
    float acc = 0.f;
#pragma unroll 8
    for (int k = 0; k < K; k += 4) {
        const float4 xv = *reinterpret_cast<const float4*>(x + k);
        acc = fmaf(xv.x, w[(k + 0) * W + jl], acc);
        acc = fmaf(xv.y, w[(k + 1) * W + jl], acc);
        acc = fmaf(xv.z, w[(k + 2) * W + jl], acc);
        acc = fmaf(xv.w, w[(k + 3) * W + jl], acc);
    }
    return acc;
}

// dynamic smem layout (floats)
#define SM_WG1 0          // 12*256  gate slice: attn (Wa | Whh)
#define SM_WG2 3072       // 12*256  gate slice: dec0
#define SM_WG3 6144       // 12*256  gate slice: dec1
#define SM_WQ  9216       // 2*256
#define SM_WP  9728       // 2*512
#define SM_WM  10752      // 4*256
#define SM_AL  11776      // 16*384 softmax/align buffer
#define SM_FLOATS 17920   // 71680 bytes

__global__ void __launch_bounds__(NTHR, 1) decoder_persistent(
    const float* __restrict__ enc, const float* __restrict__ inputs,
    const int* __restrict__ memlen,
    const float* __restrict__ w1, const float* __restrict__ b1,
    const float* __restrict__ w2, const float* __restrict__ b2,
    const float* __restrict__ memw,
    const float* __restrict__ awih, const float* __restrict__ awhh,
    const float* __restrict__ abih, const float* __restrict__ abhh,
    const float* __restrict__ qw, const float* __restrict__ av,
    const float* __restrict__ projw, const float* __restrict__ projb,
    const float* __restrict__ dwih, const float* __restrict__ dwhh,
    const float* __restrict__ dbih, const float* __restrict__ dbhh,
    const float* __restrict__ melw, const float* __restrict__ melb,
    float* __restrict__ outMel, float* __restrict__ outAlign) {
    extern __shared__ float sm[];
    const int tid = threadIdx.x;
    const int lane = tid & 31;
    const int c = blockIdx.x;
    const int gt = c * NTHR + tid;

    unsigned long long epoch = *(volatile unsigned long long*)&gEpochBase;

    // ======== P1: smem weight slices + global transposes + state zero ========
    for (int e = tid; e < 12 * 256; e += NTHR) {
        int k = e / 12, jl = e % 12;
        if (c < 64) {
            int j = c * 12 + jl;
            sm[SM_WG1 + e] = awih[j * (HH + P2D) + P2D + k];
            sm[SM_WG2 + e] = dwih[j * HH + k];
            sm[SM_WG3 + e] = dwih[(G3 + j) * HH + k];
        } else {
            int j = (c - 64) * 12 + jl;
            sm[SM_WG1 + e] = awhh[j * HH + k];
            sm[SM_WG2 + e] = dwhh[j * HH + k];
            sm[SM_WG3 + e] = dwhh[(G3 + j) * HH + k];
        }
    }
    for (int e = tid; e < 512; e += NTHR) {
        int k = e / 2, il = e % 2;
        sm[SM_WQ + e] = qw[(c * 2 + il) * HH + k];
    }
    for (int e = tid; e < 1024; e += NTHR) {
        int k = e / 2, il = e % 2;
        sm[SM_WP + e] = projw[(c * 2 + il) * (2 * HH) + k];
    }
    if (c < 100)
        for (int e = tid; e < 1024; e += NTHR) {
            int k = e / 4, ml = e % 4;
            sm[SM_WM + e] = melw[(c * 4 + ml) * HH + k];
        }

    for (int o = gt; o < BB * HH; o += GT) {
        gAttnH[o] = 0.f; gD1[o] = 0.f; gD2[o] = 0.f; gAtt[o] = 0.f;
    }
    for (int e = gt; e < MELD * HH; e += GT)
        sW1T[e] = w1[(e % HH) * MELD + e / HH];
    for (int e = gt; e < HH * P2D; e += GT)
        sW2T[e] = w2[(e % P2D) * HH + e / P2D];
    for (int e = gt; e < P2D * G3; e += GT)
        sWihPreT[e] = awih[(e % G3) * (HH + P2D) + e / G3];
    for (int e = gt; e < HH * HH; e += GT)
        sWmT[e] = memw[(e % HH) * HH + e / HH];
    for (int e = gt; e < BB * HH * TENC; e += GT) {
        int s = e % TENC, d = (e / TENC) % HH, b = e / (TENC * HH);
        sEncT[e] = enc[(b * TENC + s) * HH + d];
    }
    gbar(epoch);

    // ======== P2: processed_memory [b][s][i] + prenet layer1 ========
    for (int o = gt; o < BB * TENC * HH; o += GT) {
        int i = o % HH, sb = o / HH;
        sPm[o] = dotT<HH, HH>(sWmT, i, enc + sb * HH);
    }
    for (int o = gt; o < TDEC * BB * HH; o += GT) {
        int h = o % HH, tb = o / HH, t = tb / BB, b = tb % BB;
        float acc = b1[h];
        if (t > 0)
            acc += dotT<MELD, HH>(sW1T, h, inputs + (b * TDEC + t - 1) * MELD);
        sPn1[o] = fmaxf(acc, 0.f);
    }
    gbar(epoch);

    // ======== P3: prenet layer2 ========
    for (int o = gt; o < TDEC * BB * P2D; o += GT) {
        int p = o % P2D, tb = o / P2D;
        sPn2[o] = fmaxf(b2[p] + dotT<HH, P2D>(sW2T, p, sPn1 + tb * HH), 0.f);
    }
    gbar(epoch);

    // ======== P4: gi_pre = abih + prenet part of attn-GRU gates ========
    for (int o = gt; o < TDEC * BB * G3; o += GT) {
        int j = o % G3, tb = o / G3;
        sGiPre[o] = abih[j] + dotT<P2D, G3>(sWihPreT, j, sPn2 + tb * P2D);
    }
    gbar(epoch);

    // ================= sequential decode =================
    for (int tt = 0; tt < TDEC; tt++) {
        // -- Ph1: attention-GRU gate GEMVs (c<64: gi slice, c>=64: gh slice) --
        if (tid < 192) {
            int b = tid / 12, jl = tid % 12;
            if (c < 64) {
                int j = c * 12 + jl;
                float acc = dotS<HH, 12>(sm + SM_WG1, jl, gAtt + b * HH);
                gGiA[b * G3 + j] = sGiPre[(tt * BB + b) * G3 + j] + acc;
            } else {
                int j = (c - 64) * 12 + jl;
                float acc = dotS<HH, 12>(sm + SM_WG1, jl, gAttnH + b * HH);
                gGhA[b * G3 + j] = abhh[j] + acc;
            }
        }
        gbar(epoch);

        // -- Ph2: attn-GRU combine (32 elems per CTA, in-place) --
        if (tid < 32) {
            int o = c * 32 + tid, b = o >> 8, j = o & 255;
            const float* gi = gGiA + b * G3;
            const float* gh = gGhA + b * G3;
            float r = sigm(gi[j] + gh[j]);
            float z = sigm(gi[HH + j] + gh[HH + j]);
            float n = tanx(gi[2 * HH + j] + r * gh[2 * HH + j]);
            gAttnH[o] = (1.f - z) * n + z * gAttnH[o];
        }
        gbar(epoch);

        // -- Ph3: pq (2 cols x 16 b per CTA, split-K 4) --
        if (tid < 128) {
            int dd = tid >> 2, kq = tid & 3;
            int il = dd >> 4, b = dd & 15;
            float acc = 0.f;
            const float* x = gAttnH + b * HH + kq * 64;
            const float* w = sm + SM_WQ + kq * 64 * 2;
#pragma unroll 8
            for (int k = 0; k < 64; k += 4) {
                const float4 xv = *reinterpret_cast<const float4*>(x + k);
                acc = fmaf(xv.x, w[(k + 0) * 2 + il], acc);
                acc = fmaf(xv.y, w[(k + 1) * 2 + il], acc);
                acc = fmaf(xv.z, w[(k + 2) * 2 + il], acc);
                acc = fmaf(xv.w, w[(k + 3) * 2 + il], acc);
            }
            acc += __shfl_xor_sync(0xffffffffu, acc, 1);
            acc += __shfl_xor_sync(0xffffffffu, acc, 2);
            if (kq == 0) gPq[b * HH + c * 2 + il] = acc;
        }
        gbar(epoch);

        // -- Ph4: energies (warp per (b,s), 6 per warp) --
        {
            const int gwarp = (c << 3) + (tid >> 5);
#pragma unroll
            for (int k = 0; k < 6; k++) {
                int o = gwarp + (k << 10);              // < 6144
                int b = o / TENC, s = o - b * TENC;
                const float4* pq = reinterpret_cast<const float4*>(gPq + b * HH);
                float4 q0 = pq[lane], q1 = pq[32 + lane];
                const float4* pm =
                    reinterpret_cast<const float4*>(sPm + (b * TENC + s) * HH);
                float4 m0 = pm[lane], m1 = pm[32 + lane];
                const float4* vv = reinterpret_cast<const float4*>(av);
                float4 v0 = vv[lane], v1 = vv[32 + lane];
                float acc = v0.x * tanx(q0.x + m0.x);
                acc = fmaf(v0.y, tanx(q0.y + m0.y), acc);
                acc = fmaf(v0.z, tanx(q0.z + m0.z), acc);
                acc = fmaf(v0.w, tanx(q0.w + m0.w), acc);
                acc = fmaf(v1.x, tanx(q1.x + m1.x), acc);
                acc = fmaf(v1.y, tanx(q1.y + m1.y), acc);
                acc = fmaf(v1.z, tanx(q1.z + m1.z), acc);
                acc = fmaf(v1.w, tanx(q1.w + m1.w), acc);
#pragma unroll
                for (int off = 16; off > 0; off >>= 1)
                    acc += __shfl_xor_sync(0xffffffffu, acc, off);
                if (lane == 0)
                    gE[o] = (s < memlen[b]) ? acc : -1e30f;
            }
        }
        gbar(epoch);

        // -- Ph5: softmax (all 16 b per CTA, into smem) + context slice --
        {
            float* smAl = sm + SM_AL;
            const int w = tid >> 5;
#pragma unroll
            for (int bi = 0; bi < 2; bi++) {
                int b = 2 * w + bi;
                float v[TENC / 32];
#pragma unroll
                for (int k = 0; k < TENC / 32; k++)
                    v[k] = gE[b * TENC + lane + 32 * k];
                float m = v[0];
#pragma unroll
                for (int k = 1; k < TENC / 32; k++) m = fmaxf(m, v[k]);
#pragma unroll
                for (int off = 16; off > 0; off >>= 1)
                    m = fmaxf(m, __shfl_xor_sync(0xffffffffu, m, off));
                float sum = 0.f;
#pragma unroll
                for (int k = 0; k < TENC / 32; k++) {
                    v[k] = __expf(v[k] - m);
                    sum += v[k];
                }
#pragma unroll
                for (int off = 16; off > 0; off >>= 1)
                    sum += __shfl_xor_sync(0xffffffffu, sum, off);
                float inv = __fdividef(1.f, sum);
#pragma unroll
                for (int k = 0; k < TENC / 32; k++) {
                    float a = v[k] * inv;
                    int s = lane + 32 * k;
                    smAl[b * TENC + s] = a;
                    if (c == 0)
                        outAlign[(b * TDEC + tt) * TENC + s] = a;
                }
            }
            __syncthreads();
            if (tid < 128) {
                int dl = tid >> 6, b = (tid >> 2) & 15, q = tid & 3;
                int d = c * 2 + dl;
                const float* al = smAl + b * TENC + q * 96;
                const float* eb = sEncT + (b * HH + d) * TENC + q * 96;
                float acc = 0.f;
#pragma unroll 6
                for (int s = 0; s < 96; s += 4) {
                    const float4 a4 = *reinterpret_cast<const float4*>(al + s);
                    const float4 e4 = *reinterpret_cast<const float4*>(eb + s);
                    acc = fmaf(a4.x, e4.x, acc);
                    acc = fmaf(a4.y, e4.y, acc);
                    acc = fmaf(a4.z, e4.z, acc);
                    acc = fmaf(a4.w, e4.w, acc);
                }
                acc += __shfl_xor_sync(0xffffffffu, acc, 1);
                acc += __shfl_xor_sync(0xffffffffu, acc, 2);
                if (q == 0) gAtt[b * HH + d] = acc;
            }
        }
        gbar(epoch);

        // -- Ph6: dec_in projection (2 cols x 16 b, split-K 8 over 512) --
        {
            int dd = tid >> 3, kq = tid & 7;
            int il = dd >> 4, b = dd & 15;
            const float* x = (kq < 4) ? (gAttnH + b * HH + kq * 64)
                                      : (gAtt + b * HH + (kq - 4) * 64);
            const float* w = sm + SM_WP + kq * 64 * 2;
            float acc = 0.f;
#pragma unroll 8
            for (int k = 0; k < 64; k += 4) {
                const float4 xv = *reinterpret_cast<const float4*>(x + k);
                acc = fmaf(xv.x, w[(k + 0) * 2 + il], acc);
                acc = fmaf(xv.y, w[(k + 1) * 2 + il], acc);
                acc = fmaf(xv.z, w[(k + 2) * 2 + il], acc);
                acc = fmaf(xv.w, w[(k + 3) * 2 + il], acc);
            }
            acc += __shfl_xor_sync(0xffffffffu, acc, 1);
            acc += __shfl_xor_sync(0xffffffffu, acc, 2);
            acc += __shfl_xor_sync(0xffffffffu, acc, 4);
            if (kq == 0) {
                int i = c * 2 + il;
                gDecIn[b * HH + i] = projb[i] + acc;
            }
        }
        gbar(epoch);

        // -- Ph7: decoder GRU0 gates --
        if (tid < 192) {
            int b = tid / 12, jl = tid % 12;
            if (c < 64) {
                int j = c * 12 + jl;
                float acc = dotS<HH, 12>(sm + SM_WG2, jl, gDecIn + b * HH);
                gGiD0[b * G3 + j] = dbih[j] + acc;
            } else {
                int j = (c - 64) * 12 + jl;
                float acc = dotS<HH, 12>(sm + SM_WG2, jl, gD1 + b * HH);
                gGhD0[b * G3 + j] = dbhh[j] + acc;
            }
        }
        gbar(epoch);

        // -- Ph8: combine0 + residual --
        if (tid < 32) {
            int o = c * 32 + tid, b = o >> 8, j = o & 255;
            const float* gi = gGiD0 + b * G3;
            const float* gh = gGhD0 + b * G3;
            float r = sigm(gi[j] + gh[j]);
            float z = sigm(gi[HH + j] + gh[HH + j]);
            float n = tanx(gi[2 * HH + j] + r * gh[2 * HH + j]);
            float hnew = (1.f - z) * n + z * gD1[o];
            gD1[o] = hnew;
            gDecIn2[o] = hnew + gDecIn[o];
        }
        gbar(epoch);

        // -- Ph9: decoder GRU1 gates --
        if (tid < 192) {
            int b = tid / 12, jl = tid % 12;
            if (c < 64) {
                int j = c * 12 + jl;
                float acc = dotS<HH, 12>(sm + SM_WG3, jl, gDecIn2 + b * HH);
                gGiD1[b * G3 + j] = dbih[G3 + j] + acc;
            } else {
                int j = (c - 64) * 12 + jl;
                float acc = dotS<HH, 12>(sm + SM_WG3, jl, gD2 + b * HH);
                gGhD1[b * G3 + j] = dbhh[G3 + j] + acc;
            }
        }
        gbar(epoch);

        // -- Ph10: combine1 + residual --
        if (tid < 32) {
            int o = c * 32 + tid, b = o >> 8, j = o & 255;
            const float* gi = gGiD1 + b * G3;
            const float* gh = gGhD1 + b * G3;
            float r = sigm(gi[j] + gh[j]);
            float z = sigm(gi[HH + j] + gh[HH + j]);
            float n = tanx(gi[2 * HH + j] + r * gh[2 * HH + j]);
            float hnew = (1.f - z) * n + z * gD2[o];
            gD2[o] = hnew;
            gDecIn3[o] = hnew + gDecIn2[o];
        }
        gbar(epoch);

        // -- Ph11: mel projection (CTAs 0..99: 4 cols x 16 b, split-K 4) --
        if (c < 100) {
            int dd = tid >> 2, kq = tid & 3;
            int ml = dd >> 4, b = dd & 15;
            const float* x = gDecIn3 + b * HH + kq * 64;
            const float* w = sm + SM_WM + kq * 64 * 4;
            float acc = 0.f;
#pragma unroll 8
            for (int k = 0; k < 64; k += 4) {
                const float4 xv = *reinterpret_cast<const float4*>(x + k);
                acc = fmaf(xv.x, w[(k + 0) * 4 + ml], acc);
                acc = fmaf(xv.y, w[(k + 1) * 4 + ml], acc);
                acc = fmaf(xv.z, w[(k + 2) * 4 + ml], acc);
                acc = fmaf(xv.w, w[(k + 3) * 4 + ml], acc);
            }
            acc += __shfl_xor_sync(0xffffffffu, acc, 1);
            acc += __shfl_xor_sync(0xffffffffu, acc, 2);
            if (kq == 0) {
                int m = c * 4 + ml;
                outMel[(b * TDEC + tt) * MELD + m] = melb[m] + acc;
            }
        }
    }

    gbar(epoch);   // orders final Ph11 stores; all CTAs done
    if (c == 0 && tid == 0)
        *(volatile unsigned long long*)&gEpochBase = epoch;
}

extern "C" void kernel_launch(void* const* d_in, const int* in_sizes, int n_in,
                              void* d_out, int out_size) {
    (void)in_sizes; (void)n_in; (void)out_size;
    float* outMel = (float*)d_out;
    float* outAlign = outMel + (size_t)BB * TDEC * MELD;
    cudaFuncSetAttribute(decoder_persistent,
                         cudaFuncAttributeMaxDynamicSharedMemorySize,
                         SM_FLOATS * sizeof(float));
    decoder_persistent<<<NCTA, NTHR, SM_FLOATS * sizeof(float)>>>(
        (const float*)d_in[0], (const float*)d_in[1], (const int*)d_in[2],
        (const float*)d_in[3], (const float*)d_in[4],
        (const float*)d_in[5], (const float*)d_in[6],
        (const float*)d_in[7],
        (const float*)d_in[8], (const float*)d_in[9],
        (const float*)d_in[10], (const float*)d_in[11],
        (const float*)d_in[12], (const float*)d_in[13],
        (const float*)d_in[14], (const float*)d_in[15],
        (const float*)d_in[16], (const float*)d_in[17],
        (const float*)d_in[18], (const float*)d_in[19],
        (const float*)d_in[20], (const float*)d_in[21],
        outMel, outAlign);
}